// round 15
// baseline (speedup 1.0000x reference)
#include <cuda_runtime.h>
#include <cuda_fp16.h>
#include <cstdint>

// Problem constants
#define BB   2
#define QQ   16384
#define CC   256
#define HH   8
#define PP   4
#define DD   32
#define BEVW 128
#define BEVH 128
#define MTOT (BB*QQ)

// Scratch
__device__ __half g_v[MTOT * CC];
__device__ float  g_off[MTOT * 64];
__device__ float  g_logits[MTOT * 32];
__device__ __half g_wvh[CC * CC];
__device__ __half g_woh[CC * CC];

// ---------------------------------------------------------------------------
// PTX helpers
// ---------------------------------------------------------------------------
__device__ __forceinline__ uint32_t smem_u32(const void* p) {
    uint32_t a;
    asm("{ .reg .u64 t; cvta.to.shared.u64 t, %1; cvt.u32.u64 %0, t; }"
        : "=r"(a) : "l"(p));
    return a;
}

__device__ __forceinline__ void ldm_x4(uint32_t& r0, uint32_t& r1, uint32_t& r2,
                                       uint32_t& r3, uint32_t addr) {
    asm volatile("ldmatrix.sync.aligned.m8n8.x4.shared.b16 {%0,%1,%2,%3}, [%4];"
                 : "=r"(r0), "=r"(r1), "=r"(r2), "=r"(r3) : "r"(addr));
}

__device__ __forceinline__ void ldm_x4_trans(uint32_t& r0, uint32_t& r1, uint32_t& r2,
                                             uint32_t& r3, uint32_t addr) {
    asm volatile("ldmatrix.sync.aligned.m8n8.x4.trans.shared.b16 {%0,%1,%2,%3}, [%4];"
                 : "=r"(r0), "=r"(r1), "=r"(r2), "=r"(r3) : "r"(addr));
}

__device__ __forceinline__ void mma16816(float* c, const uint32_t* a,
                                         uint32_t b0, uint32_t b1) {
    asm volatile(
        "mma.sync.aligned.m16n8k16.row.col.f32.f16.f16.f32 "
        "{%0,%1,%2,%3}, {%4,%5,%6,%7}, {%8,%9}, {%0,%1,%2,%3};"
        : "+f"(c[0]), "+f"(c[1]), "+f"(c[2]), "+f"(c[3])
        : "r"(a[0]), "r"(a[1]), "r"(a[2]), "r"(a[3]), "r"(b0), "r"(b1));
}

__device__ __forceinline__ void cp16(uint32_t s, const void* g) {
    asm volatile("cp.async.cg.shared.global [%0], [%1], 16;" :: "r"(s), "l"(g));
}
#define CP_COMMIT() asm volatile("cp.async.commit_group;")
#define CP_WAIT1()  asm volatile("cp.async.wait_group 1;")

// ---------------------------------------------------------------------------
// Weight fp32->fp16 prologue (Wv, Wo)
// ---------------------------------------------------------------------------
__global__ __launch_bounds__(256)
void convert_weights(const float* __restrict__ Wv, const float* __restrict__ Wo,
                     __half* __restrict__ wvh, __half* __restrict__ woh)
{
    int i = blockIdx.x * 256 + threadIdx.x;
    float4 a = ((const float4*)Wv)[i];
    float4 b = ((const float4*)Wo)[i];
    uint2 ua, ub;
    __half2* ha = (__half2*)&ua;
    __half2* hb = (__half2*)&ub;
    ha[0] = __floats2half2_rn(a.x, a.y);
    ha[1] = __floats2half2_rn(a.z, a.w);
    hb[0] = __floats2half2_rn(b.x, b.y);
    hb[1] = __floats2half2_rn(b.z, b.w);
    ((uint2*)wvh)[i] = ua;
    ((uint2*)woh)[i] = ub;
}

// ---------------------------------------------------------------------------
// MERGED GEMM (R9-proven, verbatim): grid (3, 512), 128 threads.
// ---------------------------------------------------------------------------
__global__ __launch_bounds__(128, 3)
void merged_gemm_kernel(const float* __restrict__ value,
                        const __half* __restrict__ wvh,
                        const float* __restrict__ bv,
                        __half* __restrict__ vout,
                        const float* __restrict__ q,
                        const float* __restrict__ qpos,
                        const float* __restrict__ Woff,
                        const float* __restrict__ boff,
                        const float* __restrict__ Ww,
                        const float* __restrict__ bw,
                        float* __restrict__ Ooff,
                        float* __restrict__ Olog)
{
    constexpr int KG = 256, NG = 256;
    constexpr int BK = 32;

    __shared__ __align__(16) char sm[27648];
    __half* Asm = (__half*)sm;
    __half* Bsm = (__half*)(sm + 10240);

    const int tid  = threadIdx.x;
    const int warp = tid >> 5;
    const int lane = tid & 31;
    const int m0   = blockIdx.y * 64;

    if (blockIdx.x < 2) {
        const int wm = warp & 1, wn = warp >> 1;
        const int n0 = blockIdx.x * 128;

        float4 aR[4];
        uint4  bR[4];

        auto load_regs = [&](int k0) {
#pragma unroll
            for (int g = 0; g < 4; g++) {
                int idx = tid + g * 128;
                int r = idx >> 3, c4 = idx & 7;
                aR[g] = *(const float4*)(value + (size_t)(m0 + r) * KG + k0 + c4 * 4);
            }
#pragma unroll
            for (int g = 0; g < 4; g++) {
                int idx = tid + g * 128;
                int r = idx >> 4, c8 = idx & 15;
                bR[g] = *(const uint4*)(wvh + (size_t)(k0 + r) * NG + n0 + c8 * 8);
            }
        };
        auto store_smem = [&](int buf) {
#pragma unroll
            for (int g = 0; g < 4; g++) {
                int idx = tid + g * 128;
                int r = idx >> 3, c4 = idx & 7;
                __half* dst = &Asm[(buf * 64 + r) * 40 + c4 * 4];
                *(__half2*)dst       = __floats2half2_rn(aR[g].x, aR[g].y);
                *(__half2*)(dst + 2) = __floats2half2_rn(aR[g].z, aR[g].w);
            }
#pragma unroll
            for (int g = 0; g < 4; g++) {
                int idx = tid + g * 128;
                int r = idx >> 4, c8 = idx & 15;
                *(uint4*)&Bsm[(buf * 32 + r) * 136 + c8 * 8] = bR[g];
            }
        };

        float acc[2][8][4];
#pragma unroll
        for (int i = 0; i < 2; i++)
#pragma unroll
            for (int j = 0; j < 8; j++)
#pragma unroll
                for (int k = 0; k < 4; k++) acc[i][j][k] = 0.f;

        auto compute = [&](int buf) {
#pragma unroll
            for (int ks = 0; ks < 2; ks++) {
                uint32_t a[2][4];
#pragma unroll
                for (int mf = 0; mf < 2; mf++) {
                    int row = wm * 32 + mf * 16 + (lane & 15);
                    int col = ks * 16 + ((lane >> 4) << 3);
                    ldm_x4(a[mf][0], a[mf][1], a[mf][2], a[mf][3],
                           smem_u32(&Asm[(buf * 64 + row) * 40 + col]));
                }
                uint32_t b[8][2];
#pragma unroll
                for (int nb = 0; nb < 4; nb++) {
                    int g    = lane >> 3;
                    int krow = ks * 16 + ((g & 1) << 3) + (lane & 7);
                    int ncol = wn * 64 + nb * 16 + ((g >> 1) << 3);
                    ldm_x4_trans(b[2 * nb][0], b[2 * nb][1],
                                 b[2 * nb + 1][0], b[2 * nb + 1][1],
                                 smem_u32(&Bsm[(buf * 32 + krow) * 136 + ncol]));
                }
#pragma unroll
                for (int mf = 0; mf < 2; mf++)
#pragma unroll
                    for (int nf = 0; nf < 8; nf++)
                        mma16816(acc[mf][nf], a[mf], b[nf][0], b[nf][1]);
            }
        };

        load_regs(0);
        store_smem(0);
        __syncthreads();
        int cur = 0;
        for (int k0 = 0; k0 < KG; k0 += BK) {
            bool more = (k0 + BK) < KG;
            if (more) load_regs(k0 + BK);
            compute(cur);
            if (more) {
                store_smem(cur ^ 1);
                __syncthreads();
            }
            cur ^= 1;
        }

#pragma unroll
        for (int mf = 0; mf < 2; mf++) {
            int r = m0 + wm * 32 + mf * 16 + (lane >> 2);
#pragma unroll
            for (int nf = 0; nf < 8; nf++) {
                int c = n0 + wn * 64 + nf * 8 + ((lane & 3) << 1);
                float b0 = bv[c], b1 = bv[c + 1];
                size_t i0 = (size_t)r * NG + c;
                size_t i1 = (size_t)(r + 8) * NG + c;
                *(__half2*)(vout + i0) = __floats2half2_rn(acc[mf][nf][0] + b0,
                                                           acc[mf][nf][1] + b1);
                *(__half2*)(vout + i1) = __floats2half2_rn(acc[mf][nf][2] + b0,
                                                           acc[mf][nf][3] + b1);
            }
        }
    } else {
        const int wm = warp & 1, wn = warp >> 1;

        float4 aR[4], a2R[4], bR[6];

        auto load_regs = [&](int k0) {
#pragma unroll
            for (int g = 0; g < 4; g++) {
                int idx = tid + g * 128;
                int r = idx >> 3, c4 = idx & 7;
                aR[g]  = *(const float4*)(q    + (size_t)(m0 + r) * KG + k0 + c4 * 4);
                a2R[g] = *(const float4*)(qpos + (size_t)(m0 + r) * KG + k0 + c4 * 4);
            }
#pragma unroll
            for (int g = 0; g < 6; g++) {
                int idx = tid + g * 128;
                int r = idx / 24, c4 = idx % 24;
                int col = c4 * 4;
                bR[g] = (col < 64)
                    ? *(const float4*)(Woff + (size_t)(k0 + r) * 64 + col)
                    : *(const float4*)(Ww   + (size_t)(k0 + r) * 32 + col - 64);
            }
        };
        auto store_smem = [&](int buf) {
#pragma unroll
            for (int g = 0; g < 4; g++) {
                int idx = tid + g * 128;
                int r = idx >> 3, c4 = idx & 7;
                __half* dst = &Asm[(buf * 64 + r) * 40 + c4 * 4];
                *(__half2*)dst       = __floats2half2_rn(aR[g].x + a2R[g].x,
                                                         aR[g].y + a2R[g].y);
                *(__half2*)(dst + 2) = __floats2half2_rn(aR[g].z + a2R[g].z,
                                                         aR[g].w + a2R[g].w);
            }
#pragma unroll
            for (int g = 0; g < 6; g++) {
                int idx = tid + g * 128;
                int r = idx / 24, c4 = idx % 24;
                __half* dst = &Bsm[(buf * 32 + r) * 104 + c4 * 4];
                *(__half2*)dst       = __floats2half2_rn(bR[g].x, bR[g].y);
                *(__half2*)(dst + 2) = __floats2half2_rn(bR[g].z, bR[g].w);
            }
        };

        float acc[2][6][4];
#pragma unroll
        for (int i = 0; i < 2; i++)
#pragma unroll
            for (int j = 0; j < 6; j++)
#pragma unroll
                for (int k = 0; k < 4; k++) acc[i][j][k] = 0.f;

        auto compute = [&](int buf) {
#pragma unroll
            for (int ks = 0; ks < 2; ks++) {
                uint32_t a[2][4];
#pragma unroll
                for (int mf = 0; mf < 2; mf++) {
                    int row = wm * 32 + mf * 16 + (lane & 15);
                    int col = ks * 16 + ((lane >> 4) << 3);
                    ldm_x4(a[mf][0], a[mf][1], a[mf][2], a[mf][3],
                           smem_u32(&Asm[(buf * 64 + row) * 40 + col]));
                }
                uint32_t b[6][2];
#pragma unroll
                for (int nb = 0; nb < 3; nb++) {
                    int g    = lane >> 3;
                    int krow = ks * 16 + ((g & 1) << 3) + (lane & 7);
                    int ncol = wn * 48 + nb * 16 + ((g >> 1) << 3);
                    ldm_x4_trans(b[2 * nb][0], b[2 * nb][1],
                                 b[2 * nb + 1][0], b[2 * nb + 1][1],
                                 smem_u32(&Bsm[(buf * 32 + krow) * 104 + ncol]));
                }
#pragma unroll
                for (int mf = 0; mf < 2; mf++)
#pragma unroll
                    for (int nf = 0; nf < 6; nf++)
                        mma16816(acc[mf][nf], a[mf], b[nf][0], b[nf][1]);
            }
        };

        load_regs(0);
        store_smem(0);
        __syncthreads();
        int cur = 0;
        for (int k0 = 0; k0 < KG; k0 += BK) {
            bool more = (k0 + BK) < KG;
            if (more) load_regs(k0 + BK);
            compute(cur);
            if (more) {
                store_smem(cur ^ 1);
                __syncthreads();
            }
            cur ^= 1;
        }

#pragma unroll
        for (int mf = 0; mf < 2; mf++) {
            int r = m0 + wm * 32 + mf * 16 + (lane >> 2);
#pragma unroll
            for (int nf = 0; nf < 6; nf++) {
                int c = wn * 48 + nf * 8 + ((lane & 3) << 1);
                float bsv0, bsv1;
                float* O;
                int Nout, col;
                if (c < 64) { O = Ooff; Nout = 64; col = c;      bsv0 = boff[col]; bsv1 = boff[col + 1]; }
                else        { O = Olog; Nout = 32; col = c - 64; bsv0 = bw[col];   bsv1 = bw[col + 1]; }
                size_t i0 = (size_t)r * Nout + col;
                size_t i1 = (size_t)(r + 8) * Nout + col;
                *(float2*)(O + i0) = make_float2(acc[mf][nf][0] + bsv0, acc[mf][nf][1] + bsv1);
                *(float2*)(O + i1) = make_float2(acc[mf][nf][2] + bsv0, acc[mf][nf][3] + bsv1);
            }
        }
    }
}

// ---------------------------------------------------------------------------
// FUSED sampler + output GEMM.
// CTA: BM=64 rows x BN=256 (full N), 256 threads (8 warps, 2m x 4n, 32x64 tile).
// Phase 1: warps sample 64 rows of `mid` into smem (fp16, identical numerics).
// Phase 2: GEMM vs Wo (3-stage cp.async, B prefetch overlaps sampling),
//          epilogue adds bias + identity residual.
// smem: A [64][264] @0 (33792B), B 3 stages [32][264] @33792 (50688B) = 84480B.
// ---------------------------------------------------------------------------
#define FO_SMEM (33792 + 3 * 16896)

__global__ __launch_bounds__(256, 2)
void fused_sample_gemm(const __half* __restrict__ v,
                       const float* __restrict__ off,
                       const float* __restrict__ logits,
                       const float* __restrict__ ref,
                       const __half* __restrict__ Bh,
                       const float* __restrict__ bias,
                       const float* __restrict__ Res,
                       float* __restrict__ Cout)
{
    constexpr int NG = 256;
    constexpr int BK = 32;
    constexpr int NIT = 8;
    constexpr int AP = 264;   // A smem pitch (halfs)
    constexpr int BP = 264;   // B smem pitch (halfs)

    extern __shared__ __align__(16) char dsm[];
    __half* Amid = (__half*)dsm;                  // [64][AP]
    __half* Bsm  = (__half*)(dsm + 33792);        // 3 x [32][BP]

    const int tid  = threadIdx.x;
    const int warp = tid >> 5;
    const int lane = tid & 31;
    const int m0   = blockIdx.x * 64;

    auto prefetchB = [&](int it) {
        int buf = it % 3;
        int k0 = it * BK;
        // FULL stage: 32 k-rows x 256 n = 1024 16B chunks (4 groups x 256 thr)
#pragma unroll
        for (int g = 0; g < 4; g++) {
            int idx = tid + g * 256;               // 0..1023
            int r = idx >> 5, c8 = idx & 31;
            cp16(smem_u32(&Bsm[(buf * 32 + r) * BP + c8 * 8]),
                 Bh + (size_t)(k0 + r) * NG + c8 * 8);
        }
    };

    // Kick off B pipeline before sampling (overlaps with sampling compute).
    prefetchB(0); CP_COMMIT();
    prefetchB(1); CP_COMMIT();

    // ---- Phase 1: sampling. Warp w -> rows m0 + w*8 .. +7; lane=(h,chunk). ----
    const int h  = lane >> 2;
    const int d8 = (lane & 3) << 3;
    for (int i = 0; i < 8; i++) {
        const int bqloc = warp * 8 + i;
        const int bq = m0 + bqloc;
        const int b = bq >> 14;

        const float rx = __ldg(&ref[bq * 2 + 0]) * (float)BEVW - 0.5f;
        const float ry = __ldg(&ref[bq * 2 + 1]) * (float)BEVH - 0.5f;

        const float4 lg = *(const float4*)(logits + bq * 32 + h * 4);
        float mx = fmaxf(fmaxf(lg.x, lg.y), fmaxf(lg.z, lg.w));
        float e0 = __expf(lg.x - mx), e1 = __expf(lg.y - mx);
        float e2 = __expf(lg.z - mx), e3 = __expf(lg.w - mx);
        float inv = 1.f / (e0 + e1 + e2 + e3);
        float aw[4] = {e0 * inv, e1 * inv, e2 * inv, e3 * inv};

        const float4 oA = *(const float4*)(off + (size_t)bq * 64 + h * 8);
        const float4 oB = *(const float4*)(off + (size_t)bq * 64 + h * 8 + 4);
        float ox[4] = {oA.x, oA.z, oB.x, oB.z};
        float oy[4] = {oA.y, oA.w, oB.y, oB.w};

        const __half* vb = v + (size_t)b * QQ * CC + h * DD + d8;

        __half2 acc2[4];
#pragma unroll
        for (int j = 0; j < 4; j++) acc2[j] = __half2half2(__float2half(0.f));

        int ibase[4];
        __half2 wh[16];
        bool allin = true;
#pragma unroll
        for (int p = 0; p < PP; p++) {
            float x = rx + ox[p];
            float y = ry + oy[p];
            float x0f = floorf(x), y0f = floorf(y);
            float dx = x - x0f, dy = y - y0f;
            int x0 = (int)x0f, y0 = (int)y0f;
            allin &= (x0 >= 0) & (x0 <= BEVW - 2) & (y0 >= 0) & (y0 <= BEVH - 2);
            ibase[p] = ((y0 << 7) + x0) << 8;
            wh[p * 4 + 0] = __float2half2_rn(aw[p] * ((1.f - dx) * (1.f - dy)));
            wh[p * 4 + 1] = __float2half2_rn(aw[p] * (dx * (1.f - dy)));
            wh[p * 4 + 2] = __float2half2_rn(aw[p] * ((1.f - dx) * dy));
            wh[p * 4 + 3] = __float2half2_rn(aw[p] * (dx * dy));
        }

        if (__all_sync(0xffffffffu, allin)) {
            uint4 g[16];
#pragma unroll
            for (int p = 0; p < PP; p++) {
                g[p * 4 + 0] = *(const uint4*)(vb + ibase[p]);
                g[p * 4 + 1] = *(const uint4*)(vb + ibase[p] + 256);
                g[p * 4 + 2] = *(const uint4*)(vb + ibase[p] + 32768);
                g[p * 4 + 3] = *(const uint4*)(vb + ibase[p] + 33024);
            }
#pragma unroll
            for (int j = 0; j < 16; j++) {
                const __half2* gh = (const __half2*)&g[j];
#pragma unroll
                for (int k = 0; k < 4; k++)
                    acc2[k] = __hfma2(gh[k], wh[j], acc2[k]);
            }
        } else {
#pragma unroll
            for (int p = 0; p < PP; p++) {
                float x = rx + ox[p];
                float y = ry + oy[p];
                int x0 = (int)floorf(x), y0 = (int)floorf(y);
#pragma unroll
                for (int c = 0; c < 4; c++) {
                    int ix = x0 + (c & 1);
                    int iy = y0 + (c >> 1);
                    bool valid = (ix >= 0) & (ix < BEVW) & (iy >= 0) & (iy < BEVH);
                    int cx = min(max(ix, 0), BEVW - 1);
                    int cy = min(max(iy, 0), BEVH - 1);
                    __half2 w = valid ? wh[p * 4 + c] : __half2half2(__float2half(0.f));
                    const uint4 gg = *(const uint4*)(vb + (((cy << 7) + cx) << 8));
                    const __half2* gh = (const __half2*)&gg;
#pragma unroll
                    for (int k = 0; k < 4; k++)
                        acc2[k] = __hfma2(gh[k], w, acc2[k]);
                }
            }
        }

        uint4 o;
        __half2* oh = (__half2*)&o;
#pragma unroll
        for (int j = 0; j < 4; j++) oh[j] = acc2[j];
        *(uint4*)&Amid[bqloc * AP + h * DD + d8] = o;
    }
    __syncthreads();

    // ---- Phase 2: GEMM. A resident in smem; B 3-stage cp.async. ----
    const int wm = warp & 1;          // 2 m-groups of 32
    const int wn = warp >> 1;         // 4 n-groups of 64

    float acc[2][8][4];
#pragma unroll
    for (int i = 0; i < 2; i++)
#pragma unroll
        for (int j = 0; j < 8; j++)
#pragma unroll
            for (int k = 0; k < 4; k++) acc[i][j][k] = 0.f;

    for (int it = 0; it < NIT; it++) {
        CP_WAIT1();
        __syncthreads();
        if (it + 2 < NIT) prefetchB(it + 2);
        CP_COMMIT();

        const int buf = it % 3;
#pragma unroll
        for (int ks = 0; ks < 2; ks++) {
            uint32_t a[2][4];
#pragma unroll
            for (int mf = 0; mf < 2; mf++) {
                int row = wm * 32 + mf * 16 + (lane & 15);
                int col = it * BK + ks * 16 + ((lane >> 4) << 3);
                ldm_x4(a[mf][0], a[mf][1], a[mf][2], a[mf][3],
                       smem_u32(&Amid[row * AP + col]));
            }
            uint32_t b[8][2];
#pragma unroll
            for (int nb = 0; nb < 4; nb++) {
                int g    = lane >> 3;
                int krow = ks * 16 + ((g & 1) << 3) + (lane & 7);
                int ncol = wn * 64 + nb * 16 + ((g >> 1) << 3);
                ldm_x4_trans(b[2 * nb][0], b[2 * nb][1],
                             b[2 * nb + 1][0], b[2 * nb + 1][1],
                             smem_u32(&Bsm[(buf * 32 + krow) * BP + ncol]));
            }
#pragma unroll
            for (int mf = 0; mf < 2; mf++)
#pragma unroll
                for (int nf = 0; nf < 8; nf++)
                    mma16816(acc[mf][nf], a[mf], b[nf][0], b[nf][1]);
        }
        __syncthreads();
    }

    // ---- Epilogue: bias + identity residual ----
#pragma unroll
    for (int mf = 0; mf < 2; mf++) {
        int r = m0 + wm * 32 + mf * 16 + (lane >> 2);
#pragma unroll
        for (int nf = 0; nf < 8; nf++) {
            int c = wn * 64 + nf * 8 + ((lane & 3) << 1);
            float b0 = bias[c], b1 = bias[c + 1];
            size_t i0 = (size_t)r * NG + c;
            size_t i1 = (size_t)(r + 8) * NG + c;
            float2 q0 = *(const float2*)(Res + i0);
            float2 q1 = *(const float2*)(Res + i1);
            *(float2*)(Cout + i0) = make_float2(acc[mf][nf][0] + b0 + q0.x,
                                                acc[mf][nf][1] + b1 + q0.y);
            *(float2*)(Cout + i1) = make_float2(acc[mf][nf][2] + b0 + q1.x,
                                                acc[mf][nf][3] + b1 + q1.y);
        }
    }
}

// ---------------------------------------------------------------------------
// Launch
// ---------------------------------------------------------------------------
extern "C" void kernel_launch(void* const* d_in, const int* in_sizes, int n_in,
                              void* d_out, int out_size)
{
    const float* query     = (const float*)d_in[0];
    const float* value     = (const float*)d_in[1];
    const float* identity  = (const float*)d_in[2];
    const float* query_pos = (const float*)d_in[3];
    const float* refpts    = (const float*)d_in[4];
    const float* Wv   = (const float*)d_in[7];
    const float* bv   = (const float*)d_in[8];
    const float* Woff = (const float*)d_in[9];
    const float* boff = (const float*)d_in[10];
    const float* Ww   = (const float*)d_in[11];
    const float* bw   = (const float*)d_in[12];
    const float* Wo   = (const float*)d_in[13];
    const float* bo   = (const float*)d_in[14];
    float* out = (float*)d_out;

    __half *pv, *pwvh, *pwoh;
    float *poff, *plog;
    cudaGetSymbolAddress((void**)&pv,   g_v);
    cudaGetSymbolAddress((void**)&poff, g_off);
    cudaGetSymbolAddress((void**)&plog, g_logits);
    cudaGetSymbolAddress((void**)&pwvh, g_wvh);
    cudaGetSymbolAddress((void**)&pwoh, g_woh);

    cudaFuncSetAttribute(fused_sample_gemm,
                         cudaFuncAttributeMaxDynamicSharedMemorySize, FO_SMEM);

    // 0) weights fp32 -> fp16
    convert_weights<<<64, 256>>>(Wv, Wo, pwvh, pwoh);

    // 1+2+3) GEMM1 and dual GEMM in one launch
    merged_gemm_kernel<<<dim3(3, MTOT / 64), 128>>>(value, pwvh, bv, pv,
                                                    query, query_pos,
                                                    Woff, boff, Ww, bw,
                                                    poff, plog);

    // 4+5) sampling + output GEMM fused (mid never touches HBM)
    fused_sample_gemm<<<MTOT / 64, 256, FO_SMEM>>>(pv, poff, plog, refpts,
                                                   pwoh, bo, identity, out);
}

// round 16
// speedup vs baseline: 1.0620x; 1.0620x over previous
#include <cuda_runtime.h>
#include <cuda_fp16.h>
#include <cstdint>

// Problem constants
#define BB   2
#define QQ   16384
#define CC   256
#define HH   8
#define PP   4
#define DD   32
#define BEVW 128
#define BEVH 128
#define MTOT (BB*QQ)

// Scratch
__device__ __half g_v[MTOT * CC];
__device__ __half g_mid[MTOT * CC];
__device__ float  g_off[MTOT * 64];
__device__ float  g_logits[MTOT * 32];
__device__ __half g_woh[CC * CC];

// ---------------------------------------------------------------------------
// PTX helpers
// ---------------------------------------------------------------------------
__device__ __forceinline__ uint32_t smem_u32(const void* p) {
    uint32_t a;
    asm("{ .reg .u64 t; cvta.to.shared.u64 t, %1; cvt.u32.u64 %0, t; }"
        : "=r"(a) : "l"(p));
    return a;
}

__device__ __forceinline__ void ldm_x4(uint32_t& r0, uint32_t& r1, uint32_t& r2,
                                       uint32_t& r3, uint32_t addr) {
    asm volatile("ldmatrix.sync.aligned.m8n8.x4.shared.b16 {%0,%1,%2,%3}, [%4];"
                 : "=r"(r0), "=r"(r1), "=r"(r2), "=r"(r3) : "r"(addr));
}

__device__ __forceinline__ void ldm_x4_trans(uint32_t& r0, uint32_t& r1, uint32_t& r2,
                                             uint32_t& r3, uint32_t addr) {
    asm volatile("ldmatrix.sync.aligned.m8n8.x4.trans.shared.b16 {%0,%1,%2,%3}, [%4];"
                 : "=r"(r0), "=r"(r1), "=r"(r2), "=r"(r3) : "r"(addr));
}

__device__ __forceinline__ void mma16816(float* c, const uint32_t* a,
                                         uint32_t b0, uint32_t b1) {
    asm volatile(
        "mma.sync.aligned.m16n8k16.row.col.f32.f16.f16.f32 "
        "{%0,%1,%2,%3}, {%4,%5,%6,%7}, {%8,%9}, {%0,%1,%2,%3};"
        : "+f"(c[0]), "+f"(c[1]), "+f"(c[2]), "+f"(c[3])
        : "r"(a[0]), "r"(a[1]), "r"(a[2]), "r"(a[3]), "r"(b0), "r"(b1));
}

__device__ __forceinline__ void cp16(uint32_t s, const void* g) {
    asm volatile("cp.async.cg.shared.global [%0], [%1], 16;" :: "r"(s), "l"(g));
}
#define CP_COMMIT() asm volatile("cp.async.commit_group;")
#define CP_WAIT1()  asm volatile("cp.async.wait_group 1;")

// ---------------------------------------------------------------------------
// MERGED GEMM: grid (3, 512), 128 threads.
//   x<2 : GEMM1  v = value @ half(Wv) + bv -> fp16 (Wv converted inline)
//   x==2: DUAL   off/logits; also converts its slice of Wo -> g_woh.
// ---------------------------------------------------------------------------
__global__ __launch_bounds__(128, 3)
void merged_gemm_kernel(const float* __restrict__ value,
                        const float* __restrict__ Wv,
                        const float* __restrict__ bv,
                        __half* __restrict__ vout,
                        const float* __restrict__ q,
                        const float* __restrict__ qpos,
                        const float* __restrict__ Woff,
                        const float* __restrict__ boff,
                        const float* __restrict__ Ww,
                        const float* __restrict__ bw,
                        float* __restrict__ Ooff,
                        float* __restrict__ Olog,
                        const float* __restrict__ Wo,
                        __half* __restrict__ woh)
{
    constexpr int KG = 256, NG = 256;
    constexpr int BK = 32;

    __shared__ __align__(16) char sm[27648];
    __half* Asm = (__half*)sm;
    __half* Bsm = (__half*)(sm + 10240);

    const int tid  = threadIdx.x;
    const int warp = tid >> 5;
    const int lane = tid & 31;
    const int m0   = blockIdx.y * 64;

    if (blockIdx.x < 2) {
        // ================= GEMM1 (Wv fp32, inline convert) =================
        const int wm = warp & 1, wn = warp >> 1;
        const int n0 = blockIdx.x * 128;

        float4 aR[4];
        float4 bRf[8];

        auto load_regs = [&](int k0) {
#pragma unroll
            for (int g = 0; g < 4; g++) {
                int idx = tid + g * 128;
                int r = idx >> 3, c4 = idx & 7;
                aR[g] = *(const float4*)(value + (size_t)(m0 + r) * KG + k0 + c4 * 4);
            }
#pragma unroll
            for (int g = 0; g < 8; g++) {
                int idx = tid + g * 128;            // 1024 float4 chunks
                int r = idx >> 5, c4 = idx & 31;
                bRf[g] = *(const float4*)(Wv + (size_t)(k0 + r) * NG + n0 + c4 * 4);
            }
        };
        auto store_smem = [&](int buf) {
#pragma unroll
            for (int g = 0; g < 4; g++) {
                int idx = tid + g * 128;
                int r = idx >> 3, c4 = idx & 7;
                __half* dst = &Asm[(buf * 64 + r) * 40 + c4 * 4];
                *(__half2*)dst       = __floats2half2_rn(aR[g].x, aR[g].y);
                *(__half2*)(dst + 2) = __floats2half2_rn(aR[g].z, aR[g].w);
            }
#pragma unroll
            for (int g = 0; g < 8; g++) {
                int idx = tid + g * 128;
                int r = idx >> 5, c4 = idx & 31;
                __half* dst = &Bsm[(buf * 32 + r) * 136 + c4 * 4];
                *(__half2*)dst       = __floats2half2_rn(bRf[g].x, bRf[g].y);
                *(__half2*)(dst + 2) = __floats2half2_rn(bRf[g].z, bRf[g].w);
            }
        };

        float acc[2][8][4];
#pragma unroll
        for (int i = 0; i < 2; i++)
#pragma unroll
            for (int j = 0; j < 8; j++)
#pragma unroll
                for (int k = 0; k < 4; k++) acc[i][j][k] = 0.f;

        auto compute = [&](int buf) {
#pragma unroll
            for (int ks = 0; ks < 2; ks++) {
                uint32_t a[2][4];
#pragma unroll
                for (int mf = 0; mf < 2; mf++) {
                    int row = wm * 32 + mf * 16 + (lane & 15);
                    int col = ks * 16 + ((lane >> 4) << 3);
                    ldm_x4(a[mf][0], a[mf][1], a[mf][2], a[mf][3],
                           smem_u32(&Asm[(buf * 64 + row) * 40 + col]));
                }
                uint32_t b[8][2];
#pragma unroll
                for (int nb = 0; nb < 4; nb++) {
                    int g    = lane >> 3;
                    int krow = ks * 16 + ((g & 1) << 3) + (lane & 7);
                    int ncol = wn * 64 + nb * 16 + ((g >> 1) << 3);
                    ldm_x4_trans(b[2 * nb][0], b[2 * nb][1],
                                 b[2 * nb + 1][0], b[2 * nb + 1][1],
                                 smem_u32(&Bsm[(buf * 32 + krow) * 136 + ncol]));
                }
#pragma unroll
                for (int mf = 0; mf < 2; mf++)
#pragma unroll
                    for (int nf = 0; nf < 8; nf++)
                        mma16816(acc[mf][nf], a[mf], b[nf][0], b[nf][1]);
            }
        };

        load_regs(0);
        store_smem(0);
        __syncthreads();
        int cur = 0;
        for (int k0 = 0; k0 < KG; k0 += BK) {
            bool more = (k0 + BK) < KG;
            if (more) load_regs(k0 + BK);
            compute(cur);
            if (more) {
                store_smem(cur ^ 1);
                __syncthreads();
            }
            cur ^= 1;
        }

#pragma unroll
        for (int mf = 0; mf < 2; mf++) {
            int r = m0 + wm * 32 + mf * 16 + (lane >> 2);
#pragma unroll
            for (int nf = 0; nf < 8; nf++) {
                int c = n0 + wn * 64 + nf * 8 + ((lane & 3) << 1);
                float b0 = bv[c], b1 = bv[c + 1];
                size_t i0 = (size_t)r * NG + c;
                size_t i1 = (size_t)(r + 8) * NG + c;
                *(__half2*)(vout + i0) = __floats2half2_rn(acc[mf][nf][0] + b0,
                                                           acc[mf][nf][1] + b1);
                *(__half2*)(vout + i1) = __floats2half2_rn(acc[mf][nf][2] + b0,
                                                           acc[mf][nf][3] + b1);
            }
        }
    } else {
        // ================= DUAL (also converts Wo slice) =================
        // 16384 float4 of Wo / 512 CTAs = 32 per CTA; threads 0..31, 1 each.
        if (tid < 32) {
            int i = blockIdx.y * 32 + tid;
            float4 w = ((const float4*)Wo)[i];
            uint2 u;
            __half2* h = (__half2*)&u;
            h[0] = __floats2half2_rn(w.x, w.y);
            h[1] = __floats2half2_rn(w.z, w.w);
            ((uint2*)woh)[i] = u;
        }

        const int wm = warp & 1, wn = warp >> 1;

        float4 aR[4], a2R[4], bR[6];

        auto load_regs = [&](int k0) {
#pragma unroll
            for (int g = 0; g < 4; g++) {
                int idx = tid + g * 128;
                int r = idx >> 3, c4 = idx & 7;
                aR[g]  = *(const float4*)(q    + (size_t)(m0 + r) * KG + k0 + c4 * 4);
                a2R[g] = *(const float4*)(qpos + (size_t)(m0 + r) * KG + k0 + c4 * 4);
            }
#pragma unroll
            for (int g = 0; g < 6; g++) {
                int idx = tid + g * 128;
                int r = idx / 24, c4 = idx % 24;
                int col = c4 * 4;
                bR[g] = (col < 64)
                    ? *(const float4*)(Woff + (size_t)(k0 + r) * 64 + col)
                    : *(const float4*)(Ww   + (size_t)(k0 + r) * 32 + col - 64);
            }
        };
        auto store_smem = [&](int buf) {
#pragma unroll
            for (int g = 0; g < 4; g++) {
                int idx = tid + g * 128;
                int r = idx >> 3, c4 = idx & 7;
                __half* dst = &Asm[(buf * 64 + r) * 40 + c4 * 4];
                *(__half2*)dst       = __floats2half2_rn(aR[g].x + a2R[g].x,
                                                         aR[g].y + a2R[g].y);
                *(__half2*)(dst + 2) = __floats2half2_rn(aR[g].z + a2R[g].z,
                                                         aR[g].w + a2R[g].w);
            }
#pragma unroll
            for (int g = 0; g < 6; g++) {
                int idx = tid + g * 128;
                int r = idx / 24, c4 = idx % 24;
                __half* dst = &Bsm[(buf * 32 + r) * 104 + c4 * 4];
                *(__half2*)dst       = __floats2half2_rn(bR[g].x, bR[g].y);
                *(__half2*)(dst + 2) = __floats2half2_rn(bR[g].z, bR[g].w);
            }
        };

        float acc[2][6][4];
#pragma unroll
        for (int i = 0; i < 2; i++)
#pragma unroll
            for (int j = 0; j < 6; j++)
#pragma unroll
                for (int k = 0; k < 4; k++) acc[i][j][k] = 0.f;

        auto compute = [&](int buf) {
#pragma unroll
            for (int ks = 0; ks < 2; ks++) {
                uint32_t a[2][4];
#pragma unroll
                for (int mf = 0; mf < 2; mf++) {
                    int row = wm * 32 + mf * 16 + (lane & 15);
                    int col = ks * 16 + ((lane >> 4) << 3);
                    ldm_x4(a[mf][0], a[mf][1], a[mf][2], a[mf][3],
                           smem_u32(&Asm[(buf * 64 + row) * 40 + col]));
                }
                uint32_t b[6][2];
#pragma unroll
                for (int nb = 0; nb < 3; nb++) {
                    int g    = lane >> 3;
                    int krow = ks * 16 + ((g & 1) << 3) + (lane & 7);
                    int ncol = wn * 48 + nb * 16 + ((g >> 1) << 3);
                    ldm_x4_trans(b[2 * nb][0], b[2 * nb][1],
                                 b[2 * nb + 1][0], b[2 * nb + 1][1],
                                 smem_u32(&Bsm[(buf * 32 + krow) * 104 + ncol]));
                }
#pragma unroll
                for (int mf = 0; mf < 2; mf++)
#pragma unroll
                    for (int nf = 0; nf < 6; nf++)
                        mma16816(acc[mf][nf], a[mf], b[nf][0], b[nf][1]);
            }
        };

        load_regs(0);
        store_smem(0);
        __syncthreads();
        int cur = 0;
        for (int k0 = 0; k0 < KG; k0 += BK) {
            bool more = (k0 + BK) < KG;
            if (more) load_regs(k0 + BK);
            compute(cur);
            if (more) {
                store_smem(cur ^ 1);
                __syncthreads();
            }
            cur ^= 1;
        }

#pragma unroll
        for (int mf = 0; mf < 2; mf++) {
            int r = m0 + wm * 32 + mf * 16 + (lane >> 2);
#pragma unroll
            for (int nf = 0; nf < 6; nf++) {
                int c = wn * 48 + nf * 8 + ((lane & 3) << 1);
                float bsv0, bsv1;
                float* O;
                int Nout, col;
                if (c < 64) { O = Ooff; Nout = 64; col = c;      bsv0 = boff[col]; bsv1 = boff[col + 1]; }
                else        { O = Olog; Nout = 32; col = c - 64; bsv0 = bw[col];   bsv1 = bw[col + 1]; }
                size_t i0 = (size_t)r * Nout + col;
                size_t i1 = (size_t)(r + 8) * Nout + col;
                *(float2*)(O + i0) = make_float2(acc[mf][nf][0] + bsv0, acc[mf][nf][1] + bsv1);
                *(float2*)(O + i1) = make_float2(acc[mf][nf][2] + bsv0, acc[mf][nf][3] + bsv1);
            }
        }
    }
}

// ---------------------------------------------------------------------------
// GEMM5 (R9/R13-proven, verbatim): 128 thr, BM=64, BN=128, BK=32, cp.async.
// ---------------------------------------------------------------------------
__global__ __launch_bounds__(128, 4)
void hgemm_o_kernel(const __half* __restrict__ Ah,
                    const __half* __restrict__ Bh,
                    const float* __restrict__ bias,
                    const float* __restrict__ Res,
                    float* __restrict__ Cout)
{
    constexpr int KG = 256, NG = 256;
    constexpr int BK = 32;
    constexpr int NIT = KG / BK;      // 8

    __shared__ __half As[3][64][BK + 8];
    __shared__ __half Bs[3][BK][128 + 8];

    const int tid  = threadIdx.x;
    const int warp = tid >> 5;
    const int lane = tid & 31;
    const int wm   = warp & 1;
    const int wn   = warp >> 1;
    const int m0   = blockIdx.y * 64;
    const int n0   = blockIdx.x * 128;

    auto prefetch = [&](int it) {
        int buf = it % 3;
        int k0 = it * BK;
#pragma unroll
        for (int g = 0; g < 2; g++) {
            int idx = tid + g * 128;
            int r = idx >> 2, c8 = idx & 3;
            cp16(smem_u32(&As[buf][r][c8 * 8]),
                 Ah + (size_t)(m0 + r) * KG + k0 + c8 * 8);
        }
#pragma unroll
        for (int g = 0; g < 4; g++) {
            int idx = tid + g * 128;
            int r = idx >> 4, c8 = idx & 15;
            cp16(smem_u32(&Bs[buf][r][c8 * 8]),
                 Bh + (size_t)(k0 + r) * NG + n0 + c8 * 8);
        }
    };

    float acc[2][8][4];
#pragma unroll
    for (int i = 0; i < 2; i++)
#pragma unroll
        for (int j = 0; j < 8; j++)
#pragma unroll
            for (int k = 0; k < 4; k++) acc[i][j][k] = 0.f;

    auto compute = [&](int buf) {
#pragma unroll
        for (int ks = 0; ks < 2; ks++) {
            uint32_t a[2][4];
#pragma unroll
            for (int mf = 0; mf < 2; mf++) {
                int row = wm * 32 + mf * 16 + (lane & 15);
                int col = ks * 16 + ((lane >> 4) << 3);
                ldm_x4(a[mf][0], a[mf][1], a[mf][2], a[mf][3],
                       smem_u32(&As[buf][row][col]));
            }
            uint32_t b[8][2];
#pragma unroll
            for (int nb = 0; nb < 4; nb++) {
                int g    = lane >> 3;
                int krow = ks * 16 + ((g & 1) << 3) + (lane & 7);
                int ncol = wn * 64 + nb * 16 + ((g >> 1) << 3);
                ldm_x4_trans(b[2 * nb][0], b[2 * nb][1],
                             b[2 * nb + 1][0], b[2 * nb + 1][1],
                             smem_u32(&Bs[buf][krow][ncol]));
            }
#pragma unroll
            for (int mf = 0; mf < 2; mf++)
#pragma unroll
                for (int nf = 0; nf < 8; nf++)
                    mma16816(acc[mf][nf], a[mf], b[nf][0], b[nf][1]);
        }
    };

    prefetch(0); CP_COMMIT();
    prefetch(1); CP_COMMIT();
    for (int it = 0; it < NIT; it++) {
        CP_WAIT1();
        __syncthreads();
        if (it + 2 < NIT) prefetch(it + 2);
        CP_COMMIT();
        compute(it % 3);
        __syncthreads();
    }

#pragma unroll
    for (int mf = 0; mf < 2; mf++) {
        int r = m0 + wm * 32 + mf * 16 + (lane >> 2);
#pragma unroll
        for (int nf = 0; nf < 8; nf++) {
            int c = n0 + wn * 64 + nf * 8 + ((lane & 3) << 1);
            float b0 = bias[c], b1 = bias[c + 1];
            size_t i0 = (size_t)r * NG + c;
            size_t i1 = (size_t)(r + 8) * NG + c;
            float2 q0 = *(const float2*)(Res + i0);
            float2 q1 = *(const float2*)(Res + i1);
            *(float2*)(Cout + i0) = make_float2(acc[mf][nf][0] + b0 + q0.x,
                                                acc[mf][nf][1] + b1 + q0.y);
            *(float2*)(Cout + i1) = make_float2(acc[mf][nf][2] + b0 + q1.x,
                                                acc[mf][nf][3] + b1 + q1.y);
        }
    }
}

// ---------------------------------------------------------------------------
// Deformable sampling (R13-proven, verbatim): 16-deep batched fast path.
// ---------------------------------------------------------------------------
__global__ __launch_bounds__(256)
void deform_sample_kernel(const __half* __restrict__ v,
                          const float* __restrict__ off,
                          const float* __restrict__ logits,
                          const float* __restrict__ ref,
                          __half* __restrict__ mid)
{
    const int warp = threadIdx.x >> 5;
    const int lane = threadIdx.x & 31;
    const int bq   = blockIdx.x * 8 + warp;
    const int h    = lane >> 2;
    const int d8   = (lane & 3) << 3;
    const int b    = bq >> 14;

    const float rx = __ldg(&ref[bq * 2 + 0]) * (float)BEVW - 0.5f;
    const float ry = __ldg(&ref[bq * 2 + 1]) * (float)BEVH - 0.5f;

    const float4 lg = *(const float4*)(logits + bq * 32 + h * 4);
    float mx = fmaxf(fmaxf(lg.x, lg.y), fmaxf(lg.z, lg.w));
    float e0 = __expf(lg.x - mx), e1 = __expf(lg.y - mx);
    float e2 = __expf(lg.z - mx), e3 = __expf(lg.w - mx);
    float inv = 1.f / (e0 + e1 + e2 + e3);
    float aw[4] = {e0 * inv, e1 * inv, e2 * inv, e3 * inv};

    const float4 oA = *(const float4*)(off + (size_t)bq * 64 + h * 8);
    const float4 oB = *(const float4*)(off + (size_t)bq * 64 + h * 8 + 4);
    float ox[4] = {oA.x, oA.z, oB.x, oB.z};
    float oy[4] = {oA.y, oA.w, oB.y, oB.w};

    const __half* vb = v + (size_t)b * QQ * CC + h * DD + d8;

    __half2 acc2[4];
#pragma unroll
    for (int i = 0; i < 4; i++) acc2[i] = __half2half2(__float2half(0.f));

    int ibase[4];
    __half2 wh[16];
    bool allin = true;
#pragma unroll
    for (int p = 0; p < PP; p++) {
        float x = rx + ox[p];
        float y = ry + oy[p];
        float x0f = floorf(x), y0f = floorf(y);
        float dx = x - x0f, dy = y - y0f;
        int x0 = (int)x0f, y0 = (int)y0f;
        allin &= (x0 >= 0) & (x0 <= BEVW - 2) & (y0 >= 0) & (y0 <= BEVH - 2);
        ibase[p] = ((y0 << 7) + x0) << 8;
        wh[p * 4 + 0] = __float2half2_rn(aw[p] * ((1.f - dx) * (1.f - dy)));
        wh[p * 4 + 1] = __float2half2_rn(aw[p] * (dx * (1.f - dy)));
        wh[p * 4 + 2] = __float2half2_rn(aw[p] * ((1.f - dx) * dy));
        wh[p * 4 + 3] = __float2half2_rn(aw[p] * (dx * dy));
    }

    if (__all_sync(0xffffffffu, allin)) {
        uint4 g[16];
#pragma unroll
        for (int p = 0; p < PP; p++) {
            g[p * 4 + 0] = *(const uint4*)(vb + ibase[p]);
            g[p * 4 + 1] = *(const uint4*)(vb + ibase[p] + 256);
            g[p * 4 + 2] = *(const uint4*)(vb + ibase[p] + 32768);
            g[p * 4 + 3] = *(const uint4*)(vb + ibase[p] + 33024);
        }
#pragma unroll
        for (int j = 0; j < 16; j++) {
            const __half2* gh = (const __half2*)&g[j];
#pragma unroll
            for (int i = 0; i < 4; i++)
                acc2[i] = __hfma2(gh[i], wh[j], acc2[i]);
        }
    } else {
#pragma unroll
        for (int p = 0; p < PP; p++) {
            float x = rx + ox[p];
            float y = ry + oy[p];
            int x0 = (int)floorf(x), y0 = (int)floorf(y);
#pragma unroll
            for (int c = 0; c < 4; c++) {
                int ix = x0 + (c & 1);
                int iy = y0 + (c >> 1);
                bool valid = (ix >= 0) & (ix < BEVW) & (iy >= 0) & (iy < BEVH);
                int cx = min(max(ix, 0), BEVW - 1);
                int cy = min(max(iy, 0), BEVH - 1);
                __half2 w = valid ? wh[p * 4 + c] : __half2half2(__float2half(0.f));
                const uint4 gg = *(const uint4*)(vb + (((cy << 7) + cx) << 8));
                const __half2* gh = (const __half2*)&gg;
#pragma unroll
                for (int i = 0; i < 4; i++)
                    acc2[i] = __hfma2(gh[i], w, acc2[i]);
            }
        }
    }

    uint4 o;
    __half2* oh = (__half2*)&o;
#pragma unroll
    for (int i = 0; i < 4; i++) oh[i] = acc2[i];
    *(uint4*)(mid + (size_t)bq * CC + h * DD + d8) = o;
}

// ---------------------------------------------------------------------------
// Launch
// ---------------------------------------------------------------------------
extern "C" void kernel_launch(void* const* d_in, const int* in_sizes, int n_in,
                              void* d_out, int out_size)
{
    const float* query     = (const float*)d_in[0];
    const float* value     = (const float*)d_in[1];
    const float* identity  = (const float*)d_in[2];
    const float* query_pos = (const float*)d_in[3];
    const float* refpts    = (const float*)d_in[4];
    const float* Wv   = (const float*)d_in[7];
    const float* bv   = (const float*)d_in[8];
    const float* Woff = (const float*)d_in[9];
    const float* boff = (const float*)d_in[10];
    const float* Ww   = (const float*)d_in[11];
    const float* bw   = (const float*)d_in[12];
    const float* Wo   = (const float*)d_in[13];
    const float* bo   = (const float*)d_in[14];
    float* out = (float*)d_out;

    __half *pv, *pmid, *pwoh;
    float *poff, *plog;
    cudaGetSymbolAddress((void**)&pv,   g_v);
    cudaGetSymbolAddress((void**)&pmid, g_mid);
    cudaGetSymbolAddress((void**)&poff, g_off);
    cudaGetSymbolAddress((void**)&plog, g_logits);
    cudaGetSymbolAddress((void**)&pwoh, g_woh);

    // 1+2+3) GEMM1 (inline Wv convert) + dual GEMM (+ Wo convert) in one launch
    merged_gemm_kernel<<<dim3(3, MTOT / 64), 128>>>(value, Wv, bv, pv,
                                                    query, query_pos,
                                                    Woff, boff, Ww, bw,
                                                    poff, plog, Wo, pwoh);

    // 4) softmax + bilinear sampling -> fp16 mid
    deform_sample_kernel<<<MTOT / 8, 256>>>(pv, poff, plog, refpts, pmid);

    // 5) out = mid @ Wo + bo + identity
    hgemm_o_kernel<<<dim3(CC / 128, MTOT / 64), 128>>>(pmid, pwoh, bo,
                                                       identity, out);
}

// round 17
// speedup vs baseline: 1.0818x; 1.0186x over previous
#include <cuda_runtime.h>
#include <cuda_fp16.h>
#include <cstdint>

// Problem constants
#define BB   2
#define QQ   16384
#define CC   256
#define HH   8
#define PP   4
#define DD   32
#define BEVW 128
#define BEVH 128
#define MTOT (BB*QQ)

// Scratch
__device__ __half g_v[MTOT * CC];
__device__ __half g_mid[MTOT * CC];
__device__ float  g_off[MTOT * 64];
__device__ float  g_logits[MTOT * 32];
__device__ __half g_wvh[CC * CC];
__device__ __half g_woh[CC * CC];
__device__ __half g_wdual[CC * 96];    // [k][0:64)=Woff, [64:96)=Ww

// ---------------------------------------------------------------------------
// PTX helpers
// ---------------------------------------------------------------------------
__device__ __forceinline__ uint32_t smem_u32(const void* p) {
    uint32_t a;
    asm("{ .reg .u64 t; cvta.to.shared.u64 t, %1; cvt.u32.u64 %0, t; }"
        : "=r"(a) : "l"(p));
    return a;
}

__device__ __forceinline__ void ldm_x4(uint32_t& r0, uint32_t& r1, uint32_t& r2,
                                       uint32_t& r3, uint32_t addr) {
    asm volatile("ldmatrix.sync.aligned.m8n8.x4.shared.b16 {%0,%1,%2,%3}, [%4];"
                 : "=r"(r0), "=r"(r1), "=r"(r2), "=r"(r3) : "r"(addr));
}

__device__ __forceinline__ void ldm_x4_trans(uint32_t& r0, uint32_t& r1, uint32_t& r2,
                                             uint32_t& r3, uint32_t addr) {
    asm volatile("ldmatrix.sync.aligned.m8n8.x4.trans.shared.b16 {%0,%1,%2,%3}, [%4];"
                 : "=r"(r0), "=r"(r1), "=r"(r2), "=r"(r3) : "r"(addr));
}

__device__ __forceinline__ void mma16816(float* c, const uint32_t* a,
                                         uint32_t b0, uint32_t b1) {
    asm volatile(
        "mma.sync.aligned.m16n8k16.row.col.f32.f16.f16.f32 "
        "{%0,%1,%2,%3}, {%4,%5,%6,%7}, {%8,%9}, {%0,%1,%2,%3};"
        : "+f"(c[0]), "+f"(c[1]), "+f"(c[2]), "+f"(c[3])
        : "r"(a[0]), "r"(a[1]), "r"(a[2]), "r"(a[3]), "r"(b0), "r"(b1));
}

__device__ __forceinline__ void cp16(uint32_t s, const void* g) {
    asm volatile("cp.async.cg.shared.global [%0], [%1], 16;" :: "r"(s), "l"(g));
}
#define CP_COMMIT() asm volatile("cp.async.commit_group;")
#define CP_WAIT0()  asm volatile("cp.async.wait_group 0;")
#define CP_WAIT1()  asm volatile("cp.async.wait_group 1;")

// ---------------------------------------------------------------------------
// Weight fp32->fp16 prologue: Wv, Wo, and packed [Woff|Ww] (wdual).
// 38912 float4 total -> grid 152 x 256.
// ---------------------------------------------------------------------------
__global__ __launch_bounds__(256)
void convert_weights(const float* __restrict__ Wv, const float* __restrict__ Wo,
                     const float* __restrict__ Woff, const float* __restrict__ Ww,
                     __half* __restrict__ wvh, __half* __restrict__ woh,
                     __half* __restrict__ wdual)
{
    int i = blockIdx.x * 256 + threadIdx.x;   // 0..38911
    const float* src;
    __half* dst;
    if (i < 16384) {
        src = Wv + i * 4;  dst = wvh + i * 4;
    } else if (i < 32768) {
        int j = i - 16384;
        src = Wo + j * 4;  dst = woh + j * 4;
    } else {
        int j = i - 32768;               // 0..6143
        int row = j / 24, c = j % 24;
        src = (c < 16) ? (Woff + row * 64 + c * 4)
                       : (Ww   + row * 32 + (c - 16) * 4);
        dst = wdual + row * 96 + c * 4;
    }
    float4 a = *(const float4*)src;
    uint2 u;
    __half2* h = (__half2*)&u;
    h[0] = __floats2half2_rn(a.x, a.y);
    h[1] = __floats2half2_rn(a.z, a.w);
    *(uint2*)dst = u;
}

// ---------------------------------------------------------------------------
// MERGED GEMM: grid (3, 512), 128 threads. B via cp.async (fp16, no staging).
//   x<2 : GEMM1  v = value @ wvh + bv -> fp16
//   x==2: DUAL   off/logits = (q+qpos) @ wdual
// ---------------------------------------------------------------------------
__global__ __launch_bounds__(128, 3)
void merged_gemm_kernel(const float* __restrict__ value,
                        const __half* __restrict__ wvh,
                        const float* __restrict__ bv,
                        __half* __restrict__ vout,
                        const float* __restrict__ q,
                        const float* __restrict__ qpos,
                        const __half* __restrict__ wdual,
                        const float* __restrict__ boff,
                        const float* __restrict__ bw,
                        float* __restrict__ Ooff,
                        float* __restrict__ Olog)
{
    constexpr int KG = 256, NG = 256;
    constexpr int BK = 32;

    __shared__ __align__(16) char sm[27648];
    __half* Asm = (__half*)sm;                 // 2 bufs x 64 x 40
    __half* Bsm = (__half*)(sm + 10240);

    const int tid  = threadIdx.x;
    const int warp = tid >> 5;
    const int lane = tid & 31;
    const int m0   = blockIdx.y * 64;

    if (blockIdx.x < 2) {
        // ================= GEMM1 =================
        const int wm = warp & 1, wn = warp >> 1;
        const int n0 = blockIdx.x * 128;

        float4 aR[4];

        auto loadA = [&](int k0) {
#pragma unroll
            for (int g = 0; g < 4; g++) {
                int idx = tid + g * 128;
                int r = idx >> 3, c4 = idx & 7;
                aR[g] = *(const float4*)(value + (size_t)(m0 + r) * KG + k0 + c4 * 4);
            }
        };
        auto cpB = [&](int k0, int buf) {
#pragma unroll
            for (int g = 0; g < 4; g++) {
                int idx = tid + g * 128;           // 512 16B chunks
                int r = idx >> 4, c8 = idx & 15;
                cp16(smem_u32(&Bsm[(buf * 32 + r) * 136 + c8 * 8]),
                     wvh + (size_t)(k0 + r) * NG + n0 + c8 * 8);
            }
        };
        auto storeA = [&](int buf) {
#pragma unroll
            for (int g = 0; g < 4; g++) {
                int idx = tid + g * 128;
                int r = idx >> 3, c4 = idx & 7;
                __half* dst = &Asm[(buf * 64 + r) * 40 + c4 * 4];
                *(__half2*)dst       = __floats2half2_rn(aR[g].x, aR[g].y);
                *(__half2*)(dst + 2) = __floats2half2_rn(aR[g].z, aR[g].w);
            }
        };

        float acc[2][8][4];
#pragma unroll
        for (int i = 0; i < 2; i++)
#pragma unroll
            for (int j = 0; j < 8; j++)
#pragma unroll
                for (int k = 0; k < 4; k++) acc[i][j][k] = 0.f;

        auto compute = [&](int buf) {
#pragma unroll
            for (int ks = 0; ks < 2; ks++) {
                uint32_t a[2][4];
#pragma unroll
                for (int mf = 0; mf < 2; mf++) {
                    int row = wm * 32 + mf * 16 + (lane & 15);
                    int col = ks * 16 + ((lane >> 4) << 3);
                    ldm_x4(a[mf][0], a[mf][1], a[mf][2], a[mf][3],
                           smem_u32(&Asm[(buf * 64 + row) * 40 + col]));
                }
                uint32_t b[8][2];
#pragma unroll
                for (int nb = 0; nb < 4; nb++) {
                    int g    = lane >> 3;
                    int krow = ks * 16 + ((g & 1) << 3) + (lane & 7);
                    int ncol = wn * 64 + nb * 16 + ((g >> 1) << 3);
                    ldm_x4_trans(b[2 * nb][0], b[2 * nb][1],
                                 b[2 * nb + 1][0], b[2 * nb + 1][1],
                                 smem_u32(&Bsm[(buf * 32 + krow) * 136 + ncol]));
                }
#pragma unroll
                for (int mf = 0; mf < 2; mf++)
#pragma unroll
                    for (int nf = 0; nf < 8; nf++)
                        mma16816(acc[mf][nf], a[mf], b[nf][0], b[nf][1]);
            }
        };

        loadA(0);
        cpB(0, 0); CP_COMMIT();
        storeA(0);
        CP_WAIT0();
        __syncthreads();
        int cur = 0;
        for (int k0 = 0; k0 < KG; k0 += BK) {
            bool more = (k0 + BK) < KG;
            if (more) {
                loadA(k0 + BK);
                cpB(k0 + BK, cur ^ 1); CP_COMMIT();
            }
            compute(cur);
            if (more) {
                storeA(cur ^ 1);
                CP_WAIT0();
                __syncthreads();
            }
            cur ^= 1;
        }

#pragma unroll
        for (int mf = 0; mf < 2; mf++) {
            int r = m0 + wm * 32 + mf * 16 + (lane >> 2);
#pragma unroll
            for (int nf = 0; nf < 8; nf++) {
                int c = n0 + wn * 64 + nf * 8 + ((lane & 3) << 1);
                float b0 = bv[c], b1 = bv[c + 1];
                size_t i0 = (size_t)r * NG + c;
                size_t i1 = (size_t)(r + 8) * NG + c;
                *(__half2*)(vout + i0) = __floats2half2_rn(acc[mf][nf][0] + b0,
                                                           acc[mf][nf][1] + b1);
                *(__half2*)(vout + i1) = __floats2half2_rn(acc[mf][nf][2] + b0,
                                                           acc[mf][nf][3] + b1);
            }
        }
    } else {
        // ================= DUAL =================
        const int wm = warp & 1, wn = warp >> 1;

        float4 aR[4], a2R[4];

        auto loadA = [&](int k0) {
#pragma unroll
            for (int g = 0; g < 4; g++) {
                int idx = tid + g * 128;
                int r = idx >> 3, c4 = idx & 7;
                aR[g]  = *(const float4*)(q    + (size_t)(m0 + r) * KG + k0 + c4 * 4);
                a2R[g] = *(const float4*)(qpos + (size_t)(m0 + r) * KG + k0 + c4 * 4);
            }
        };
        auto cpB = [&](int k0, int buf) {
#pragma unroll
            for (int g = 0; g < 3; g++) {
                int idx = tid + g * 128;           // 384 16B chunks
                int r = idx / 12, c8 = idx % 12;
                cp16(smem_u32(&Bsm[(buf * 32 + r) * 104 + c8 * 8]),
                     wdual + (size_t)(k0 + r) * 96 + c8 * 8);
            }
        };
        auto storeA = [&](int buf) {
#pragma unroll
            for (int g = 0; g < 4; g++) {
                int idx = tid + g * 128;
                int r = idx >> 3, c4 = idx & 7;
                __half* dst = &Asm[(buf * 64 + r) * 40 + c4 * 4];
                *(__half2*)dst       = __floats2half2_rn(aR[g].x + a2R[g].x,
                                                         aR[g].y + a2R[g].y);
                *(__half2*)(dst + 2) = __floats2half2_rn(aR[g].z + a2R[g].z,
                                                         aR[g].w + a2R[g].w);
            }
        };

        float acc[2][6][4];
#pragma unroll
        for (int i = 0; i < 2; i++)
#pragma unroll
            for (int j = 0; j < 6; j++)
#pragma unroll
                for (int k = 0; k < 4; k++) acc[i][j][k] = 0.f;

        auto compute = [&](int buf) {
#pragma unroll
            for (int ks = 0; ks < 2; ks++) {
                uint32_t a[2][4];
#pragma unroll
                for (int mf = 0; mf < 2; mf++) {
                    int row = wm * 32 + mf * 16 + (lane & 15);
                    int col = ks * 16 + ((lane >> 4) << 3);
                    ldm_x4(a[mf][0], a[mf][1], a[mf][2], a[mf][3],
                           smem_u32(&Asm[(buf * 64 + row) * 40 + col]));
                }
                uint32_t b[6][2];
#pragma unroll
                for (int nb = 0; nb < 3; nb++) {
                    int g    = lane >> 3;
                    int krow = ks * 16 + ((g & 1) << 3) + (lane & 7);
                    int ncol = wn * 48 + nb * 16 + ((g >> 1) << 3);
                    ldm_x4_trans(b[2 * nb][0], b[2 * nb][1],
                                 b[2 * nb + 1][0], b[2 * nb + 1][1],
                                 smem_u32(&Bsm[(buf * 32 + krow) * 104 + ncol]));
                }
#pragma unroll
                for (int mf = 0; mf < 2; mf++)
#pragma unroll
                    for (int nf = 0; nf < 6; nf++)
                        mma16816(acc[mf][nf], a[mf], b[nf][0], b[nf][1]);
            }
        };

        loadA(0);
        cpB(0, 0); CP_COMMIT();
        storeA(0);
        CP_WAIT0();
        __syncthreads();
        int cur = 0;
        for (int k0 = 0; k0 < KG; k0 += BK) {
            bool more = (k0 + BK) < KG;
            if (more) {
                loadA(k0 + BK);
                cpB(k0 + BK, cur ^ 1); CP_COMMIT();
            }
            compute(cur);
            if (more) {
                storeA(cur ^ 1);
                CP_WAIT0();
                __syncthreads();
            }
            cur ^= 1;
        }

#pragma unroll
        for (int mf = 0; mf < 2; mf++) {
            int r = m0 + wm * 32 + mf * 16 + (lane >> 2);
#pragma unroll
            for (int nf = 0; nf < 6; nf++) {
                int c = wn * 48 + nf * 8 + ((lane & 3) << 1);
                float bsv0, bsv1;
                float* O;
                int Nout, col;
                if (c < 64) { O = Ooff; Nout = 64; col = c;      bsv0 = boff[col]; bsv1 = boff[col + 1]; }
                else        { O = Olog; Nout = 32; col = c - 64; bsv0 = bw[col];   bsv1 = bw[col + 1]; }
                size_t i0 = (size_t)r * Nout + col;
                size_t i1 = (size_t)(r + 8) * Nout + col;
                *(float2*)(O + i0) = make_float2(acc[mf][nf][0] + bsv0, acc[mf][nf][1] + bsv1);
                *(float2*)(O + i1) = make_float2(acc[mf][nf][2] + bsv0, acc[mf][nf][3] + bsv1);
            }
        }
    }
}

// ---------------------------------------------------------------------------
// GEMM5 (R9/R13-proven, verbatim): 128 thr, BM=64, BN=128, BK=32, cp.async.
// ---------------------------------------------------------------------------
__global__ __launch_bounds__(128, 4)
void hgemm_o_kernel(const __half* __restrict__ Ah,
                    const __half* __restrict__ Bh,
                    const float* __restrict__ bias,
                    const float* __restrict__ Res,
                    float* __restrict__ Cout)
{
    constexpr int KG = 256, NG = 256;
    constexpr int BK = 32;
    constexpr int NIT = KG / BK;      // 8

    __shared__ __half As[3][64][BK + 8];
    __shared__ __half Bs[3][BK][128 + 8];

    const int tid  = threadIdx.x;
    const int warp = tid >> 5;
    const int lane = tid & 31;
    const int wm   = warp & 1;
    const int wn   = warp >> 1;
    const int m0   = blockIdx.y * 64;
    const int n0   = blockIdx.x * 128;

    auto prefetch = [&](int it) {
        int buf = it % 3;
        int k0 = it * BK;
#pragma unroll
        for (int g = 0; g < 2; g++) {
            int idx = tid + g * 128;
            int r = idx >> 2, c8 = idx & 3;
            cp16(smem_u32(&As[buf][r][c8 * 8]),
                 Ah + (size_t)(m0 + r) * KG + k0 + c8 * 8);
        }
#pragma unroll
        for (int g = 0; g < 4; g++) {
            int idx = tid + g * 128;
            int r = idx >> 4, c8 = idx & 15;
            cp16(smem_u32(&Bs[buf][r][c8 * 8]),
                 Bh + (size_t)(k0 + r) * NG + n0 + c8 * 8);
        }
    };

    float acc[2][8][4];
#pragma unroll
    for (int i = 0; i < 2; i++)
#pragma unroll
        for (int j = 0; j < 8; j++)
#pragma unroll
            for (int k = 0; k < 4; k++) acc[i][j][k] = 0.f;

    auto compute = [&](int buf) {
#pragma unroll
        for (int ks = 0; ks < 2; ks++) {
            uint32_t a[2][4];
#pragma unroll
            for (int mf = 0; mf < 2; mf++) {
                int row = wm * 32 + mf * 16 + (lane & 15);
                int col = ks * 16 + ((lane >> 4) << 3);
                ldm_x4(a[mf][0], a[mf][1], a[mf][2], a[mf][3],
                       smem_u32(&As[buf][row][col]));
            }
            uint32_t b[8][2];
#pragma unroll
            for (int nb = 0; nb < 4; nb++) {
                int g    = lane >> 3;
                int krow = ks * 16 + ((g & 1) << 3) + (lane & 7);
                int ncol = wn * 64 + nb * 16 + ((g >> 1) << 3);
                ldm_x4_trans(b[2 * nb][0], b[2 * nb][1],
                             b[2 * nb + 1][0], b[2 * nb + 1][1],
                             smem_u32(&Bs[buf][krow][ncol]));
            }
#pragma unroll
            for (int mf = 0; mf < 2; mf++)
#pragma unroll
                for (int nf = 0; nf < 8; nf++)
                    mma16816(acc[mf][nf], a[mf], b[nf][0], b[nf][1]);
        }
    };

    prefetch(0); CP_COMMIT();
    prefetch(1); CP_COMMIT();
    for (int it = 0; it < NIT; it++) {
        CP_WAIT1();
        __syncthreads();
        if (it + 2 < NIT) prefetch(it + 2);
        CP_COMMIT();
        compute(it % 3);
        __syncthreads();
    }

#pragma unroll
    for (int mf = 0; mf < 2; mf++) {
        int r = m0 + wm * 32 + mf * 16 + (lane >> 2);
#pragma unroll
        for (int nf = 0; nf < 8; nf++) {
            int c = n0 + wn * 64 + nf * 8 + ((lane & 3) << 1);
            float b0 = bias[c], b1 = bias[c + 1];
            size_t i0 = (size_t)r * NG + c;
            size_t i1 = (size_t)(r + 8) * NG + c;
            float2 q0 = *(const float2*)(Res + i0);
            float2 q1 = *(const float2*)(Res + i1);
            *(float2*)(Cout + i0) = make_float2(acc[mf][nf][0] + b0 + q0.x,
                                                acc[mf][nf][1] + b1 + q0.y);
            *(float2*)(Cout + i1) = make_float2(acc[mf][nf][2] + b0 + q1.x,
                                                acc[mf][nf][3] + b1 + q1.y);
        }
    }
}

// ---------------------------------------------------------------------------
// Deformable sampling (R13-proven, verbatim): 16-deep batched fast path.
// ---------------------------------------------------------------------------
__global__ __launch_bounds__(256)
void deform_sample_kernel(const __half* __restrict__ v,
                          const float* __restrict__ off,
                          const float* __restrict__ logits,
                          const float* __restrict__ ref,
                          __half* __restrict__ mid)
{
    const int warp = threadIdx.x >> 5;
    const int lane = threadIdx.x & 31;
    const int bq   = blockIdx.x * 8 + warp;
    const int h    = lane >> 2;
    const int d8   = (lane & 3) << 3;
    const int b    = bq >> 14;

    const float rx = __ldg(&ref[bq * 2 + 0]) * (float)BEVW - 0.5f;
    const float ry = __ldg(&ref[bq * 2 + 1]) * (float)BEVH - 0.5f;

    const float4 lg = *(const float4*)(logits + bq * 32 + h * 4);
    float mx = fmaxf(fmaxf(lg.x, lg.y), fmaxf(lg.z, lg.w));
    float e0 = __expf(lg.x - mx), e1 = __expf(lg.y - mx);
    float e2 = __expf(lg.z - mx), e3 = __expf(lg.w - mx);
    float inv = 1.f / (e0 + e1 + e2 + e3);
    float aw[4] = {e0 * inv, e1 * inv, e2 * inv, e3 * inv};

    const float4 oA = *(const float4*)(off + (size_t)bq * 64 + h * 8);
    const float4 oB = *(const float4*)(off + (size_t)bq * 64 + h * 8 + 4);
    float ox[4] = {oA.x, oA.z, oB.x, oB.z};
    float oy[4] = {oA.y, oA.w, oB.y, oB.w};

    const __half* vb = v + (size_t)b * QQ * CC + h * DD + d8;

    __half2 acc2[4];
#pragma unroll
    for (int i = 0; i < 4; i++) acc2[i] = __half2half2(__float2half(0.f));

    int ibase[4];
    __half2 wh[16];
    bool allin = true;
#pragma unroll
    for (int p = 0; p < PP; p++) {
        float x = rx + ox[p];
        float y = ry + oy[p];
        float x0f = floorf(x), y0f = floorf(y);
        float dx = x - x0f, dy = y - y0f;
        int x0 = (int)x0f, y0 = (int)y0f;
        allin &= (x0 >= 0) & (x0 <= BEVW - 2) & (y0 >= 0) & (y0 <= BEVH - 2);
        ibase[p] = ((y0 << 7) + x0) << 8;
        wh[p * 4 + 0] = __float2half2_rn(aw[p] * ((1.f - dx) * (1.f - dy)));
        wh[p * 4 + 1] = __float2half2_rn(aw[p] * (dx * (1.f - dy)));
        wh[p * 4 + 2] = __float2half2_rn(aw[p] * ((1.f - dx) * dy));
        wh[p * 4 + 3] = __float2half2_rn(aw[p] * (dx * dy));
    }

    if (__all_sync(0xffffffffu, allin)) {
        uint4 g[16];
#pragma unroll
        for (int p = 0; p < PP; p++) {
            g[p * 4 + 0] = *(const uint4*)(vb + ibase[p]);
            g[p * 4 + 1] = *(const uint4*)(vb + ibase[p] + 256);
            g[p * 4 + 2] = *(const uint4*)(vb + ibase[p] + 32768);
            g[p * 4 + 3] = *(const uint4*)(vb + ibase[p] + 33024);
        }
#pragma unroll
        for (int j = 0; j < 16; j++) {
            const __half2* gh = (const __half2*)&g[j];
#pragma unroll
            for (int i = 0; i < 4; i++)
                acc2[i] = __hfma2(gh[i], wh[j], acc2[i]);
        }
    } else {
#pragma unroll
        for (int p = 0; p < PP; p++) {
            float x = rx + ox[p];
            float y = ry + oy[p];
            int x0 = (int)floorf(x), y0 = (int)floorf(y);
#pragma unroll
            for (int c = 0; c < 4; c++) {
                int ix = x0 + (c & 1);
                int iy = y0 + (c >> 1);
                bool valid = (ix >= 0) & (ix < BEVW) & (iy >= 0) & (iy < BEVH);
                int cx = min(max(ix, 0), BEVW - 1);
                int cy = min(max(iy, 0), BEVH - 1);
                __half2 w = valid ? wh[p * 4 + c] : __half2half2(__float2half(0.f));
                const uint4 gg = *(const uint4*)(vb + (((cy << 7) + cx) << 8));
                const __half2* gh = (const __half2*)&gg;
#pragma unroll
                for (int i = 0; i < 4; i++)
                    acc2[i] = __hfma2(gh[i], w, acc2[i]);
            }
        }
    }

    uint4 o;
    __half2* oh = (__half2*)&o;
#pragma unroll
    for (int i = 0; i < 4; i++) oh[i] = acc2[i];
    *(uint4*)(mid + (size_t)bq * CC + h * DD + d8) = o;
}

// ---------------------------------------------------------------------------
// Launch
// ---------------------------------------------------------------------------
extern "C" void kernel_launch(void* const* d_in, const int* in_sizes, int n_in,
                              void* d_out, int out_size)
{
    const float* query     = (const float*)d_in[0];
    const float* value     = (const float*)d_in[1];
    const float* identity  = (const float*)d_in[2];
    const float* query_pos = (const float*)d_in[3];
    const float* refpts    = (const float*)d_in[4];
    const float* Wv   = (const float*)d_in[7];
    const float* bv   = (const float*)d_in[8];
    const float* Woff = (const float*)d_in[9];
    const float* boff = (const float*)d_in[10];
    const float* Ww   = (const float*)d_in[11];
    const float* bw   = (const float*)d_in[12];
    const float* Wo   = (const float*)d_in[13];
    const float* bo   = (const float*)d_in[14];
    float* out = (float*)d_out;

    __half *pv, *pmid, *pwvh, *pwoh, *pwd;
    float *poff, *plog;
    cudaGetSymbolAddress((void**)&pv,   g_v);
    cudaGetSymbolAddress((void**)&pmid, g_mid);
    cudaGetSymbolAddress((void**)&poff, g_off);
    cudaGetSymbolAddress((void**)&plog, g_logits);
    cudaGetSymbolAddress((void**)&pwvh, g_wvh);
    cudaGetSymbolAddress((void**)&pwoh, g_woh);
    cudaGetSymbolAddress((void**)&pwd,  g_wdual);

    // 0) all weights fp32 -> fp16 (Wv, Wo, packed [Woff|Ww])
    convert_weights<<<152, 256>>>(Wv, Wo, Woff, Ww, pwvh, pwoh, pwd);

    // 1+2+3) GEMM1 and dual GEMM in one launch (B via cp.async, no staging)
    merged_gemm_kernel<<<dim3(3, MTOT / 64), 128>>>(value, pwvh, bv, pv,
                                                    query, query_pos, pwd,
                                                    boff, bw, poff, plog);

    // 4) softmax + bilinear sampling -> fp16 mid
    deform_sample_kernel<<<MTOT / 8, 256>>>(pv, poff, plog, refpts, pmid);

    // 5) out = mid @ Wo + bo + identity
    hgemm_o_kernel<<<dim3(CC / 128, MTOT / 64), 128>>>(pmid, pwoh, bo,
                                                       identity, out);
}